// round 16
// baseline (speedup 1.0000x reference)
#include <cuda_runtime.h>
#include <cuda_bf16.h>
#include <cuda_fp16.h>
#include <math.h>

#define NSAMP 64
#define CIN   512
#define TT    64
#define NPAIR 2016
#define PAIR_BLOCKS 280
#define PAIR_SMEM_BYTES (98304 + 16)
#define PREPW_SMEM_BYTES ((32 * 512 + 256 * 9 + 256) * 4)
#define FEAT_SMEM_BYTES (65536 + 16)

typedef unsigned long long ull;
typedef unsigned int u32;

__device__ __forceinline__ ull pack2(float lo, float hi) {
    ull r;
    asm("mov.b64 %0, {%1, %2};" : "=l"(r) : "f"(lo), "f"(hi));
    return r;
}
__device__ __forceinline__ void unpack2(ull v, float &lo, float &hi) {
    asm("mov.b64 {%0, %1}, %2;" : "=f"(lo), "=f"(hi) : "l"(v));
}
__device__ __forceinline__ ull fma2(ull a, ull b, ull c) {
    ull d;
    asm("fma.rn.f32x2 %0, %1, %2, %3;" : "=l"(d) : "l"(a), "l"(b), "l"(c));
    return d;
}
__device__ __forceinline__ u32 smem_u32(const void* p) {
    u32 a;
    asm("{ .reg .u64 t; cvta.to.shared.u64 t, %1; cvt.u32.u64 %0, t; }" : "=r"(a) : "l"(p));
    return a;
}

#define LDSM4(r, addr) \
    asm volatile("ldmatrix.sync.aligned.m8n8.x4.shared.b16 {%0,%1,%2,%3}, [%4];" \
        : "=r"((r)[0]), "=r"((r)[1]), "=r"((r)[2]), "=r"((r)[3]) : "r"(addr))

#define LDSM4T(r, addr) \
    asm volatile("ldmatrix.sync.aligned.m8n8.x4.trans.shared.b16 {%0,%1,%2,%3}, [%4];" \
        : "=r"((r)[0]), "=r"((r)[1]), "=r"((r)[2]), "=r"((r)[3]) : "r"(addr))

#define MMA4(d, a, b0v, b1v) \
    asm volatile("mma.sync.aligned.m16n8k16.row.col.f32.bf16.bf16.f32 " \
        "{%0,%1,%2,%3}, {%4,%5,%6,%7}, {%8,%9}, {%0,%1,%2,%3};" \
        : "+f"((d)[0]), "+f"((d)[1]), "+f"((d)[2]), "+f"((d)[3]) \
        : "r"((a)[0]), "r"((a)[1]), "r"((a)[2]), "r"((a)[3]), "r"(b0v), "r"(b1v))

#define MMA4H(d, a, b0v, b1v) \
    asm volatile("mma.sync.aligned.m16n8k16.row.col.f32.f16.f16.f32 " \
        "{%0,%1,%2,%3}, {%4,%5,%6,%7}, {%8,%9}, {%0,%1,%2,%3};" \
        : "+f"((d)[0]), "+f"((d)[1]), "+f"((d)[2]), "+f"((d)[3]) \
        : "r"((a)[0]), "r"((a)[1]), "r"((a)[2]), "r"((a)[3]), "r"(b0v), "r"(b1v))

#define BULK_G2S(dst, src, bytes, mbar) \
    asm volatile("cp.async.bulk.shared::cluster.global.mbarrier::complete_tx::bytes [%0], [%1], %2, [%3];" \
        :: "r"(dst), "l"(src), "r"(bytes), "r"(mbar) : "memory")

#define MBAR_INIT(mbar, cnt) \
    asm volatile("mbarrier.init.shared.b64 [%0], %1;" :: "r"(mbar), "r"(cnt) : "memory")

#define MBAR_EXPECT(mbar, bytes) \
    asm volatile("mbarrier.arrive.expect_tx.shared.b64 _, [%0], %1;" :: "r"(mbar), "r"(bytes) : "memory")

#define MBAR_WAIT(mbar, parity) do { \
    u32 _done; \
    asm volatile("{\n\t.reg .pred p;\n\t" \
        "mbarrier.try_wait.parity.acquire.cta.shared::cta.b64 p, [%1], %2;\n\t" \
        "selp.b32 %0, 1, 0, p;\n\t}" : "=r"(_done) : "r"(mbar), "r"(parity) : "memory"); \
    if (!_done) { \
        asm volatile("{\n\t.reg .pred P1;\n\t" \
            "WL_%=:\n\t" \
            "mbarrier.try_wait.parity.acquire.cta.shared::cta.b64 P1, [%0], %1, 0x989680;\n\t" \
            "@P1 bra.uni WD_%=;\n\tbra.uni WL_%=;\n\tWD_%=:\n\t}" \
            :: "r"(mbar), "r"(parity) : "memory"); \
    } \
} while (0)

__device__ __forceinline__ void split2(float v0, float v1, u32& h, u32& l) {
    __nv_bfloat162 hb = __floats2bfloat162_rn(v0, v1);
    float2 hf = __bfloat1622float2(hb);
    __nv_bfloat162 lb = __floats2bfloat162_rn(v0 - hf.x, v1 - hf.y);
    h = *(u32*)&hb;
    l = *(u32*)&lb;
}

// Scratch (device globals; no allocation allowed)
__device__ __align__(16) float g_biasAll[320];
// W tiles chunk-major: [rg(5)][kc(8)][64 rows][128B], byte = (kl*2)^((rl&7)<<4)
__device__ __align__(16) __nv_bfloat16 g_WH[320 * 512];
__device__ __align__(16) __nv_bfloat16 g_WL[320 * 512];
// x tiles: [n][k=512][t=64] bf16, 128B rows, byte = (t*2)^((k&7)<<4) — chunk-contiguous
__device__ __align__(16) __nv_bfloat16 g_xH[NSAMP * 64 * 512];
__device__ __align__(16) __nv_bfloat16 g_xL[NSAMP * 64 * 512];
// A tiles: [n][hw=128][t'=128] fp16, 256B rows, swizzle ^((hw&7)<<4)
__device__ __align__(16) __half g_FeF[NSAMP * 16384];
// B tiles: [n][o=32][t'=128] fp16, 256B rows, swizzle ^((o&7)<<4)
__device__ __align__(16) __half g_GF[NSAMP * 4096];
__device__ __align__(16) float g_scorePart[NSAMP * 2];

__device__ __forceinline__ u32 w_off(int row, int kg) {
    int rg = row >> 6, rl = row & 63, kc = kg >> 6, kl = kg & 63;
    return (u32)(((rg * 8 + kc) * 64 + rl) * 128) + (((u32)(kl * 2)) ^ (((u32)rl & 7) << 4));
}

// ---------------------------------------------------------------------------
// prep_x: 128 blocks = (n, k-half), no dynamic smem. Streaming x split + score.
// ---------------------------------------------------------------------------
__global__ __launch_bounds__(512) void prep_x_kernel(const float* __restrict__ x,
                                                     const float* __restrict__ w_mlp) {
    __shared__ float red[16];
    int idx = blockIdx.x;
    int n = idx >> 1, h = idx & 1;
    int tid = threadIdx.x;
    const float4* xg = (const float4*)(x + (size_t)n * 32768 + (size_t)h * 16384);
    const float4* wg = (const float4*)(w_mlp + (size_t)h * 16384);
    char* xh = (char*)g_xH + (size_t)n * 65536;
    char* xl = (char*)g_xL + (size_t)n * 65536;
    float spart = 0.f;
    #pragma unroll 4
    for (int i = tid; i < 4096; i += 512) {
        int c = i >> 4, t4 = i & 15;
        float4 xv = xg[i];
        float4 wv = wg[i];
        spart += xv.x * wv.x + xv.y * wv.y + xv.z * wv.z + xv.w * wv.w;
        int k = h * 256 + c;
        u32 h0, l0, h1, l1;
        split2(xv.x, xv.y, h0, l0);
        split2(xv.z, xv.w, h1, l1);
        u32 base = (u32)k * 128 + (((u32)(t4 * 8)) ^ (((u32)k & 7) << 4));
        *(ull*)(xh + base) = (ull)h0 | ((ull)h1 << 32);
        *(ull*)(xl + base) = (ull)l0 | ((ull)l1 << 32);
    }
    #pragma unroll
    for (int off = 16; off > 0; off >>= 1)
        spart += __shfl_xor_sync(0xffffffffu, spart, off);
    if ((tid & 31) == 0) red[tid >> 5] = spart;
    __syncthreads();
    if (tid == 0) {
        float t = 0.f;
        #pragma unroll
        for (int w = 0; w < 16; ++w) t += red[w];
        g_scorePart[n * 2 + h] = t;
    }
}

// ---------------------------------------------------------------------------
// prep_w: 64 blocks x 8 k columns. Fused weights (bf16 hi/lo chunk-major) + bias.
// ---------------------------------------------------------------------------
__global__ __launch_bounds__(512) void prep_w_kernel(const float* __restrict__ w_conv1d,
                            const float* __restrict__ b_conv1d,
                            const float* __restrict__ w_c1) {
    extern __shared__ float psm[];
    int b = blockIdx.x;
    int tid = threadIdx.x;

    float* w1_sm = psm;
    float* wc_sm = psm + 16384;
    float* b_sm  = psm + 16384 + 2304;
    int c0 = b * 8;

    {
        const float4* src = (const float4*)w_c1;
        float4* dst = (float4*)w1_sm;
        #pragma unroll
        for (int k = 0; k < 8; ++k) dst[tid + k * 512] = src[tid + k * 512];
    }
    {
        int c = tid >> 1, k4 = tid & 1;
        float4 v = *(const float4*)(w_conv1d + c * 512 + c0 + k4 * 4);
        wc_sm[c * 9 + k4 * 4 + 0] = v.x;
        wc_sm[c * 9 + k4 * 4 + 1] = v.y;
        wc_sm[c * 9 + k4 * 4 + 2] = v.z;
        wc_sm[c * 9 + k4 * 4 + 3] = v.w;
    }
    if (b == 0 && tid < 256) b_sm[tid] = b_conv1d[tid];
    __syncthreads();

    // rows 0..255 -> bf16 hi/lo (chunk-major layout)
    #pragma unroll
    for (int q = 0; q < 4; ++q) {
        int idx = tid + q * 512;
        int kk = idx >> 8, c = idx & 255;
        float v = wc_sm[c * 9 + kk];
        __nv_bfloat16 hb = __float2bfloat16(v);
        __nv_bfloat16 lb = __float2bfloat16(v - __bfloat162float(hb));
        u32 off = w_off(c, c0 + kk);
        *(__nv_bfloat16*)((char*)g_WH + off) = hb;
        *(__nv_bfloat16*)((char*)g_WL + off) = lb;
    }

    // fused A/B rows 256..319
    {
        int half = tid & 1, k = (tid >> 1) & 7, o = tid >> 4;
        int cbase = half * 128;
        const ull* w1p = (const ull*)(w1_sm + o * 512) + cbase;
        const float* wcp = wc_sm + cbase * 9 + k;
        ull acc0 = 0ULL, acc1 = 0ULL;
        #pragma unroll 8
        for (int c = 0; c < 128; c += 2) {
            float w0 = wcp[c * 9];
            float w1v = wcp[(c + 1) * 9];
            acc0 = fma2(w1p[c], pack2(w0, w0), acc0);
            acc1 = fma2(w1p[c + 1], pack2(w1v, w1v), acc1);
        }
        float l0, h0, l1, h1;
        unpack2(acc0, l0, h0);
        unpack2(acc1, l1, h1);
        float sl = l0 + l1, sh = h0 + h1;
        float pl = __shfl_xor_sync(0xffffffffu, sl, 1);
        float ph = __shfl_xor_sync(0xffffffffu, sh, 1);
        if (half == 0) {
            int kg = c0 + k;
            float vA = sl + pl;
            float vB = sh + ph;
            __nv_bfloat16 hA = __float2bfloat16(vA);
            __nv_bfloat16 lA = __float2bfloat16(vA - __bfloat162float(hA));
            __nv_bfloat16 hB = __float2bfloat16(vB);
            __nv_bfloat16 lB = __float2bfloat16(vB - __bfloat162float(hB));
            u32 offA = w_off(256 + o, kg);
            u32 offB = w_off(288 + o, kg);
            *(__nv_bfloat16*)((char*)g_WH + offA) = hA;
            *(__nv_bfloat16*)((char*)g_WL + offA) = lA;
            *(__nv_bfloat16*)((char*)g_WH + offB) = hB;
            *(__nv_bfloat16*)((char*)g_WL + offB) = lB;
        }
    }

    if (b == 0) {
        int wid = tid >> 5, lane = tid & 31;
        if (wid < 8) {
            #pragma unroll
            for (int s = 0; s < 8; ++s) {
                int row = wid * 8 + s;
                int kind = row >> 5, o = row & 31;
                float p = 0.f;
                #pragma unroll
                for (int cc = 0; cc < 8; ++cc) {
                    int c = lane + 32 * cc;
                    p += w1_sm[o * 512 + 2 * c + kind] * b_sm[c];
                }
                #pragma unroll
                for (int off = 16; off > 0; off >>= 1)
                    p += __shfl_xor_sync(0xffffffffu, p, off);
                if (lane == 0) g_biasAll[256 + kind * 32 + o] = p;
            }
        }
        if (tid < 256) g_biasAll[tid] = b_sm[tid];
    }
}

// ---------------------------------------------------------------------------
// feat (bf16 3-pass, bulk-async staged): 320 CTAs = 5 rg x 64 n, 256 threads.
// ---------------------------------------------------------------------------
__global__ __launch_bounds__(256) void feat_kernel() {
    extern __shared__ char fsm[];
    u32 sbase = smem_u32(fsm);
    int bx = blockIdx.x;
    int rg = bx >> 6, n = bx & 63;
    int tid = threadIdx.x, wid = tid >> 5, la = tid & 31;
    int wm = wid & 1, wn = wid >> 1;

    const char* wH = (const char*)g_WH + (size_t)rg * 65536;
    const char* wL = (const char*)g_WL + (size_t)rg * 65536;
    const char* xH = (const char*)g_xH + (size_t)n * 65536;
    const char* xL = (const char*)g_xL + (size_t)n * 65536;

    u32 mb0 = sbase + 65536, mb1 = sbase + 65544;
    if (tid == 0) {
        MBAR_INIT(mb0, 1u);
        MBAR_INIT(mb1, 1u);
    }
    __syncthreads();

    auto issue = [&](int kc, int buf) {
        u32 db = sbase + buf * 32768;
        u32 mb = buf ? mb1 : mb0;
        MBAR_EXPECT(mb, 32768u);
        BULK_G2S(db,         wH + (size_t)kc * 8192, 8192u, mb);
        BULK_G2S(db + 8192,  wL + (size_t)kc * 8192, 8192u, mb);
        BULK_G2S(db + 16384, xH + (size_t)kc * 8192, 8192u, mb);
        BULK_G2S(db + 24576, xL + (size_t)kc * 8192, 8192u, mb);
    };

    if (tid == 0) {
        issue(0, 0);
        issue(1, 1);
    }

    float acc[2][2][4];
    #pragma unroll
    for (int mt = 0; mt < 2; ++mt)
        #pragma unroll
        for (int nt = 0; nt < 2; ++nt)
            #pragma unroll
            for (int e = 0; e < 4; ++e) acc[mt][nt][e] = 0.f;

    int mrow_base = wm * 32 + (la & 7) + ((la >> 3) & 1) * 8;
    int a_kx = (la >> 4) * 16;
    int krow_loc = (la & 7) + ((la >> 3) & 1) * 8;
    int t_sw = (wn * 32 + ((la >> 4) & 1) * 16) ^ ((la & 7) << 4);

    int ph0 = 0, ph1 = 0;
    #pragma unroll 1
    for (int kc = 0; kc < 8; ++kc) {
        int buf = kc & 1;
        if (buf) { MBAR_WAIT(mb1, ph1); ph1 ^= 1; }
        else     { MBAR_WAIT(mb0, ph0); ph0 ^= 1; }
        u32 base = sbase + buf * 32768;
        u32 WHo = base, WLo = base + 8192, XHo = base + 16384, XLo = base + 24576;
        #pragma unroll
        for (int kk = 0; kk < 4; ++kk) {
            int kb = kk * 32;
            u32 offB = (u32)((kk * 16 + krow_loc) * 128) + (u32)t_sw;
            u32 bH[4], bL[4];
            LDSM4T(bH, XHo + offB);
            LDSM4T(bL, XLo + offB);
            #pragma unroll
            for (int mt = 0; mt < 2; ++mt) {
                int mr = mrow_base + mt * 16;
                u32 offA = (u32)mr * 128 + (((u32)(kb + a_kx)) ^ (((u32)mr & 7) << 4));
                u32 aH[4], aL[4];
                LDSM4(aH, WHo + offA);
                LDSM4(aL, WLo + offA);
                #pragma unroll
                for (int nt = 0; nt < 2; ++nt) {
                    int r0 = nt * 2;
                    MMA4(acc[mt][nt], aH, bH[r0], bH[r0 + 1]);
                    MMA4(acc[mt][nt], aH, bL[r0], bL[r0 + 1]);
                    MMA4(acc[mt][nt], aL, bH[r0], bH[r0 + 1]);
                }
            }
        }
        __syncthreads();
        if (kc + 2 < 8 && tid == 0) issue(kc + 2, buf);
    }

    char* feF = (char*)g_FeF + (size_t)n * 32768;
    char* gF  = (char*)g_GF + (size_t)n * 8192;
    int r0l = la >> 2, c0l = (la & 3) * 2;

    #pragma unroll
    for (int mt = 0; mt < 2; ++mt) {
        #pragma unroll
        for (int nt = 0; nt < 2; ++nt) {
            int t0 = wn * 16 + nt * 8 + c0l;
            #pragma unroll
            for (int hh = 0; hh < 2; ++hh) {
                int row = rg * 64 + wm * 32 + mt * 16 + r0l + hh * 8;
                float bias = g_biasAll[row];
                float v0 = acc[mt][nt][hh * 2 + 0] + bias;
                float v1 = acc[mt][nt][hh * 2 + 1] + bias;
                __half2 hv = __floats2half2_rn(v0, v1);
                u32 hbits = *(u32*)&hv;
                if (row < 256) {
                    int hw = row & 127;
                    int tp0 = (row < 128) ? t0 : (64 + t0);
                    u32 off = (u32)hw * 256 + (((u32)(tp0 * 2)) ^ (((u32)hw & 7) << 4));
                    *(u32*)(feF + off) = hbits;
                } else {
                    int o = (row < 288) ? (row - 256) : (row - 288);
                    int tp0 = (row < 288) ? t0 : (64 + t0);
                    u32 off = (u32)o * 256 + (((u32)(tp0 * 2)) ^ (((u32)o & 7) << 4));
                    *(u32*)(gF + off) = hbits;
                }
            }
        }
    }
}

// ---------------------------------------------------------------------------
// pair (fp16 single-pass, bulk-async staged): 280 blocks x 8 pairs, 2 CTA/SM.
// ---------------------------------------------------------------------------
__global__ __launch_bounds__(512)
void pair_kernel(const float* __restrict__ b_c1,
                 const float* __restrict__ w_c2, const float* __restrict__ b_c2,
                 const float* __restrict__ w_fc1, const float* __restrict__ b_fc1,
                 const float* __restrict__ w_fc2, const float* __restrict__ b_fc2,
                 const float* __restrict__ w_fc3, const float* __restrict__ b_fc3,
                 const float* __restrict__ b_mlp,
                 float* __restrict__ out) {
    extern __shared__ char smem[];
    float* smf = (float*)smem;
    u32 sbase = smem_u32(smem);
    int tid = threadIdx.x;
    int wid = tid >> 5, la = tid & 31;
    int b = blockIdx.x;

    int j = 1, bb = b;
    while (bb >= ((j + 7) >> 3)) { bb -= (j + 7) >> 3; ++j; }
    int i0 = bb * 8;

    u32 mb = sbase + 98304;
    if (tid == 0) MBAR_INIT(mb, 1u);
    __syncthreads();
    if (tid == 0) {
        MBAR_EXPECT(mb, 98304u);
        BULK_G2S(sbase, (const char*)g_FeF + (size_t)j * 32768, 32768u, mb);
        #pragma unroll
        for (int u = 0; u < 8; ++u) {
            int iu = i0 + u; if (iu >= j) iu = j - 1;
            BULK_G2S(sbase + 32768 + u * 8192, (const char*)g_GF + (size_t)iu * 8192, 8192u, mb);
        }
    }

    if (b < NSAMP && tid == 300) {
        float z = g_scorePart[2 * b] + g_scorePart[2 * b + 1] + b_mlp[0];
        out[b] = 1.f / (1.f + expf(-z));
    }

    MBAR_WAIT(mb, 0u);

    int p = wid >> 1, half = wid & 1;
    u32 A_f = sbase;
    u32 B_f = sbase + 32768 + p * 8192;

    int mrow_base = half * 64 + (la & 7) + ((la >> 3) & 1) * 8;
    int a_kx = (la >> 4) * 16;
    int orow0 = ((la >> 4) & 1) * 8 + (la & 7);
    int b_kx = ((la >> 3) & 1) * 16;

    float acc[4][4][4];
    #pragma unroll
    for (int mt = 0; mt < 4; ++mt)
        #pragma unroll
        for (int nt = 0; nt < 4; ++nt)
            #pragma unroll
            for (int e = 0; e < 4; ++e) acc[mt][nt][e] = 0.f;

    #pragma unroll 1
    for (int ks = 0; ks < 8; ++ks) {
        int kb = ks * 32;
        u32 bF[2][4];
        #pragma unroll
        for (int q = 0; q < 2; ++q) {
            int orow = orow0 + q * 16;
            u32 off = (u32)orow * 256 + (((u32)(kb + b_kx)) ^ (((u32)orow & 7) << 4));
            LDSM4(bF[q], B_f + off);
        }
        #pragma unroll
        for (int mt = 0; mt < 4; ++mt) {
            int mr = mrow_base + mt * 16;
            u32 off = (u32)mr * 256 + (((u32)(kb + a_kx)) ^ (((u32)mr & 7) << 4));
            u32 aF[4];
            LDSM4(aF, A_f + off);
            #pragma unroll
            for (int nt = 0; nt < 4; ++nt) {
                int q = nt >> 1, r0 = (nt & 1) * 2;
                MMA4H(acc[mt][nt], aF, bF[q][r0], bF[q][r0 + 1]);
            }
        }
    }

    float bo[4][2];
    #pragma unroll
    for (int nt = 0; nt < 4; ++nt) {
        int o = nt * 8 + (la & 3) * 2;
        bo[nt][0] = b_c1[o];
        bo[nt][1] = b_c1[o + 1];
    }
    int r = la >> 2;
    bool writer = ((r & 5) == 0);
    int pw = (r >> 1) & 1;
    float* pool = smf + 8192 + p * 2048;

    asm volatile("bar.sync %0, 64;" :: "r"(1 + p));

    #pragma unroll
    for (int mt = 0; mt < 4; ++mt) {
        int ph0 = half * 8 + mt * 2;
        #pragma unroll
        for (int nt = 0; nt < 4; ++nt) {
            float v0 = acc[mt][nt][0], v1 = acc[mt][nt][1];
            float v2 = acc[mt][nt][2], v3 = acc[mt][nt][3];
            v0 = fmaxf(v0, __shfl_xor_sync(0xffffffffu, v0, 4));
            v0 = fmaxf(v0, __shfl_xor_sync(0xffffffffu, v0, 16));
            v1 = fmaxf(v1, __shfl_xor_sync(0xffffffffu, v1, 4));
            v1 = fmaxf(v1, __shfl_xor_sync(0xffffffffu, v1, 16));
            v2 = fmaxf(v2, __shfl_xor_sync(0xffffffffu, v2, 4));
            v2 = fmaxf(v2, __shfl_xor_sync(0xffffffffu, v2, 16));
            v3 = fmaxf(v3, __shfl_xor_sync(0xffffffffu, v3, 4));
            v3 = fmaxf(v3, __shfl_xor_sync(0xffffffffu, v3, 16));
            if (writer) {
                int o = nt * 8 + (la & 3) * 2;
                int s01 = ph0 * 2 + pw, s23 = (ph0 + 1) * 2 + pw;
                pool[s01 * 33 + o]     = v0 + bo[nt][0];
                pool[s01 * 33 + o + 1] = v1 + bo[nt][1];
                pool[s23 * 33 + o]     = v2 + bo[nt][0];
                pool[s23 * 33 + o + 1] = v3 + bo[nt][1];
            }
        }
    }

    int u = tid >> 6, t64 = tid & 63;
    bool valid = (i0 + u) < j;
    float* g2 = pool + 1056;
    float* vv = pool + 1312;
    float* v1s = pool + 1376;
    float* v2s = pool + 1408;
    int bar = 1 + u;

    asm volatile("bar.sync %0, 64;" :: "r"(bar));

    #pragma unroll
    for (int k = 0; k < 4; ++k) {
        int idx = t64 + k * 64;
        int o2 = idx >> 5, s2 = idx & 31;
        float sum = b_c2[o2];
        const float* wr = w_c2 + o2 * 32;
        #pragma unroll
        for (int oo = 0; oo < 32; ++oo)
            sum += wr[oo] * pool[s2 * 33 + oo];
        g2[o2 * 32 + s2] = sum;
    }
    asm volatile("bar.sync %0, 64;" :: "r"(bar));

    {
        int o2 = t64 >> 3, q = t64 & 7;
        const float* gb = g2 + o2 * 32 + q * 4;
        vv[t64] = fmaxf(fmaxf(gb[0], gb[1]), fmaxf(gb[2], gb[3]));
    }
    asm volatile("bar.sync %0, 64;" :: "r"(bar));

    if (t64 < 32) {
        float z = b_fc1[t64];
        #pragma unroll
        for (int m = 0; m < 64; ++m) z += w_fc1[t64 * 64 + m] * vv[m];
        v1s[t64] = fmaxf(z, 0.f);
    }
    asm volatile("bar.sync %0, 64;" :: "r"(bar));
    if (t64 < 8) {
        float z = b_fc2[t64];
        #pragma unroll
        for (int m = 0; m < 32; ++m) z += w_fc2[t64 * 32 + m] * v1s[m];
        v2s[t64] = fmaxf(z, 0.f);
    }
    asm volatile("bar.sync %0, 64;" :: "r"(bar));
    if (t64 == 0 && valid) {
        float z = b_fc3[0];
        #pragma unroll
        for (int m = 0; m < 8; ++m) z += w_fc3[m] * v2s[m];
        int i = i0 + u;
        int pidx = i * (2 * NSAMP - i - 1) / 2 + (j - i - 1);
        out[NSAMP + pidx] = 1.f / (1.f + expf(-z));
    }
}

extern "C" void kernel_launch(void* const* d_in, const int* in_sizes, int n_in,
                              void* d_out, int out_size) {
    const float* x        = (const float*)d_in[0];
    const float* w_conv1d = (const float*)d_in[1];
    const float* b_conv1d = (const float*)d_in[2];
    const float* w_c1     = (const float*)d_in[3];
    const float* b_c1     = (const float*)d_in[4];
    const float* w_c2     = (const float*)d_in[5];
    const float* b_c2     = (const float*)d_in[6];
    const float* w_fc1    = (const float*)d_in[7];
    const float* b_fc1    = (const float*)d_in[8];
    const float* w_fc2    = (const float*)d_in[9];
    const float* b_fc2    = (const float*)d_in[10];
    const float* w_fc3    = (const float*)d_in[11];
    const float* b_fc3    = (const float*)d_in[12];
    const float* w_mlp    = (const float*)d_in[13];
    const float* b_mlp    = (const float*)d_in[14];
    float* out = (float*)d_out;

    cudaFuncSetAttribute(prep_w_kernel, cudaFuncAttributeMaxDynamicSharedMemorySize, PREPW_SMEM_BYTES);
    cudaFuncSetAttribute(feat_kernel, cudaFuncAttributeMaxDynamicSharedMemorySize, FEAT_SMEM_BYTES);
    cudaFuncSetAttribute(pair_kernel, cudaFuncAttributeMaxDynamicSharedMemorySize, PAIR_SMEM_BYTES);

    prep_x_kernel<<<128, 512>>>(x, w_mlp);
    prep_w_kernel<<<64, 512, PREPW_SMEM_BYTES>>>(w_conv1d, b_conv1d, w_c1);
    feat_kernel<<<320, 256, FEAT_SMEM_BYTES>>>();
    pair_kernel<<<PAIR_BLOCKS, 512, PAIR_SMEM_BYTES>>>(b_c1, w_c2, b_c2, w_fc1, b_fc1,
                                                       w_fc2, b_fc2, w_fc3, b_fc3, b_mlp, out);
}

// round 17
// speedup vs baseline: 1.3280x; 1.3280x over previous
#include <cuda_runtime.h>
#include <cuda_bf16.h>
#include <cuda_fp16.h>
#include <math.h>

#define NSAMP 64
#define CIN   512
#define TT    64
#define NPAIR 2016
#define PAIR_BLOCKS 280
// A 32768 | B 8x8192 | mbar 16 | epi tables ~10.5KB
#define EPI_F (24584)
#define PAIR_SMEM_BYTES ((EPI_F + 2640) * 4)
#define PREPW_SMEM_BYTES ((32 * 512 + 256 * 9 + 256) * 4)
#define FEAT_SMEM_BYTES (65536 + 16)

typedef unsigned long long ull;
typedef unsigned int u32;

__device__ __forceinline__ ull pack2(float lo, float hi) {
    ull r;
    asm("mov.b64 %0, {%1, %2};" : "=l"(r) : "f"(lo), "f"(hi));
    return r;
}
__device__ __forceinline__ void unpack2(ull v, float &lo, float &hi) {
    asm("mov.b64 {%0, %1}, %2;" : "=f"(lo), "=f"(hi) : "l"(v));
}
__device__ __forceinline__ ull fma2(ull a, ull b, ull c) {
    ull d;
    asm("fma.rn.f32x2 %0, %1, %2, %3;" : "=l"(d) : "l"(a), "l"(b), "l"(c));
    return d;
}
__device__ __forceinline__ u32 smem_u32(const void* p) {
    u32 a;
    asm("{ .reg .u64 t; cvta.to.shared.u64 t, %1; cvt.u32.u64 %0, t; }" : "=r"(a) : "l"(p));
    return a;
}

#define LDSM4(r, addr) \
    asm volatile("ldmatrix.sync.aligned.m8n8.x4.shared.b16 {%0,%1,%2,%3}, [%4];" \
        : "=r"((r)[0]), "=r"((r)[1]), "=r"((r)[2]), "=r"((r)[3]) : "r"(addr))

#define LDSM4T(r, addr) \
    asm volatile("ldmatrix.sync.aligned.m8n8.x4.trans.shared.b16 {%0,%1,%2,%3}, [%4];" \
        : "=r"((r)[0]), "=r"((r)[1]), "=r"((r)[2]), "=r"((r)[3]) : "r"(addr))

#define MMA4(d, a, b0v, b1v) \
    asm volatile("mma.sync.aligned.m16n8k16.row.col.f32.bf16.bf16.f32 " \
        "{%0,%1,%2,%3}, {%4,%5,%6,%7}, {%8,%9}, {%0,%1,%2,%3};" \
        : "+f"((d)[0]), "+f"((d)[1]), "+f"((d)[2]), "+f"((d)[3]) \
        : "r"((a)[0]), "r"((a)[1]), "r"((a)[2]), "r"((a)[3]), "r"(b0v), "r"(b1v))

#define MMA4H(d, a, b0v, b1v) \
    asm volatile("mma.sync.aligned.m16n8k16.row.col.f32.f16.f16.f32 " \
        "{%0,%1,%2,%3}, {%4,%5,%6,%7}, {%8,%9}, {%0,%1,%2,%3};" \
        : "+f"((d)[0]), "+f"((d)[1]), "+f"((d)[2]), "+f"((d)[3]) \
        : "r"((a)[0]), "r"((a)[1]), "r"((a)[2]), "r"((a)[3]), "r"(b0v), "r"(b1v))

#define BULK_G2S(dst, src, bytes, mbar) \
    asm volatile("cp.async.bulk.shared::cluster.global.mbarrier::complete_tx::bytes [%0], [%1], %2, [%3];" \
        :: "r"(dst), "l"(src), "r"(bytes), "r"(mbar) : "memory")

#define MBAR_INIT(mbar, cnt) \
    asm volatile("mbarrier.init.shared.b64 [%0], %1;" :: "r"(mbar), "r"(cnt) : "memory")

#define MBAR_EXPECT(mbar, bytes) \
    asm volatile("mbarrier.arrive.expect_tx.shared.b64 _, [%0], %1;" :: "r"(mbar), "r"(bytes) : "memory")

#define MBAR_WAIT(mbar, parity) do { \
    u32 _done; \
    asm volatile("{\n\t.reg .pred p;\n\t" \
        "mbarrier.try_wait.parity.acquire.cta.shared::cta.b64 p, [%1], %2;\n\t" \
        "selp.b32 %0, 1, 0, p;\n\t}" : "=r"(_done) : "r"(mbar), "r"(parity) : "memory"); \
    if (!_done) { \
        asm volatile("{\n\t.reg .pred P1;\n\t" \
            "WL_%=:\n\t" \
            "mbarrier.try_wait.parity.acquire.cta.shared::cta.b64 P1, [%0], %1, 0x989680;\n\t" \
            "@P1 bra.uni WD_%=;\n\tbra.uni WL_%=;\n\tWD_%=:\n\t}" \
            :: "r"(mbar), "r"(parity) : "memory"); \
    } \
} while (0)

__device__ __forceinline__ void split2(float v0, float v1, u32& h, u32& l) {
    __nv_bfloat162 hb = __floats2bfloat162_rn(v0, v1);
    float2 hf = __bfloat1622float2(hb);
    __nv_bfloat162 lb = __floats2bfloat162_rn(v0 - hf.x, v1 - hf.y);
    h = *(u32*)&hb;
    l = *(u32*)&lb;
}

// Scratch (device globals; no allocation allowed)
__device__ __align__(16) float g_biasAll[320];
__device__ __align__(16) __nv_bfloat16 g_WH[320 * 512];
__device__ __align__(16) __nv_bfloat16 g_WL[320 * 512];
__device__ __align__(16) __nv_bfloat16 g_xH[NSAMP * 64 * 512];
__device__ __align__(16) __nv_bfloat16 g_xL[NSAMP * 64 * 512];
__device__ __align__(16) __half g_FeF[NSAMP * 16384];
__device__ __align__(16) __half g_GF[NSAMP * 4096];
__device__ __align__(16) float g_scorePart[NSAMP * 2];

__device__ __forceinline__ u32 w_off(int row, int kg) {
    int rg = row >> 6, rl = row & 63, kc = kg >> 6, kl = kg & 63;
    return (u32)(((rg * 8 + kc) * 64 + rl) * 128) + (((u32)(kl * 2)) ^ (((u32)rl & 7) << 4));
}

// ---------------------------------------------------------------------------
// prep_x: 128 blocks, streaming x split + score partial.
// ---------------------------------------------------------------------------
__global__ __launch_bounds__(512) void prep_x_kernel(const float* __restrict__ x,
                                                     const float* __restrict__ w_mlp) {
    __shared__ float red[16];
    int idx = blockIdx.x;
    int n = idx >> 1, h = idx & 1;
    int tid = threadIdx.x;
    const float4* xg = (const float4*)(x + (size_t)n * 32768 + (size_t)h * 16384);
    const float4* wg = (const float4*)(w_mlp + (size_t)h * 16384);
    char* xh = (char*)g_xH + (size_t)n * 65536;
    char* xl = (char*)g_xL + (size_t)n * 65536;
    float spart = 0.f;
    #pragma unroll 4
    for (int i = tid; i < 4096; i += 512) {
        int c = i >> 4, t4 = i & 15;
        float4 xv = xg[i];
        float4 wv = wg[i];
        spart += xv.x * wv.x + xv.y * wv.y + xv.z * wv.z + xv.w * wv.w;
        int k = h * 256 + c;
        u32 h0, l0, h1, l1;
        split2(xv.x, xv.y, h0, l0);
        split2(xv.z, xv.w, h1, l1);
        u32 base = (u32)k * 128 + (((u32)(t4 * 8)) ^ (((u32)k & 7) << 4));
        *(ull*)(xh + base) = (ull)h0 | ((ull)h1 << 32);
        *(ull*)(xl + base) = (ull)l0 | ((ull)l1 << 32);
    }
    #pragma unroll
    for (int off = 16; off > 0; off >>= 1)
        spart += __shfl_xor_sync(0xffffffffu, spart, off);
    if ((tid & 31) == 0) red[tid >> 5] = spart;
    __syncthreads();
    if (tid == 0) {
        float t = 0.f;
        #pragma unroll
        for (int w = 0; w < 16; ++w) t += red[w];
        g_scorePart[n * 2 + h] = t;
    }
}

// ---------------------------------------------------------------------------
// prep_w: 64 blocks x 8 k columns. Fused weights + bias.
// ---------------------------------------------------------------------------
__global__ __launch_bounds__(512) void prep_w_kernel(const float* __restrict__ w_conv1d,
                            const float* __restrict__ b_conv1d,
                            const float* __restrict__ w_c1) {
    extern __shared__ float psm[];
    int b = blockIdx.x;
    int tid = threadIdx.x;

    float* w1_sm = psm;
    float* wc_sm = psm + 16384;
    float* b_sm  = psm + 16384 + 2304;
    int c0 = b * 8;

    {
        const float4* src = (const float4*)w_c1;
        float4* dst = (float4*)w1_sm;
        #pragma unroll
        for (int k = 0; k < 8; ++k) dst[tid + k * 512] = src[tid + k * 512];
    }
    {
        int c = tid >> 1, k4 = tid & 1;
        float4 v = *(const float4*)(w_conv1d + c * 512 + c0 + k4 * 4);
        wc_sm[c * 9 + k4 * 4 + 0] = v.x;
        wc_sm[c * 9 + k4 * 4 + 1] = v.y;
        wc_sm[c * 9 + k4 * 4 + 2] = v.z;
        wc_sm[c * 9 + k4 * 4 + 3] = v.w;
    }
    if (b == 0 && tid < 256) b_sm[tid] = b_conv1d[tid];
    __syncthreads();

    #pragma unroll
    for (int q = 0; q < 4; ++q) {
        int idx = tid + q * 512;
        int kk = idx >> 8, c = idx & 255;
        float v = wc_sm[c * 9 + kk];
        __nv_bfloat16 hb = __float2bfloat16(v);
        __nv_bfloat16 lb = __float2bfloat16(v - __bfloat162float(hb));
        u32 off = w_off(c, c0 + kk);
        *(__nv_bfloat16*)((char*)g_WH + off) = hb;
        *(__nv_bfloat16*)((char*)g_WL + off) = lb;
    }

    {
        int half = tid & 1, k = (tid >> 1) & 7, o = tid >> 4;
        int cbase = half * 128;
        const ull* w1p = (const ull*)(w1_sm + o * 512) + cbase;
        const float* wcp = wc_sm + cbase * 9 + k;
        ull acc0 = 0ULL, acc1 = 0ULL;
        #pragma unroll 8
        for (int c = 0; c < 128; c += 2) {
            float w0 = wcp[c * 9];
            float w1v = wcp[(c + 1) * 9];
            acc0 = fma2(w1p[c], pack2(w0, w0), acc0);
            acc1 = fma2(w1p[c + 1], pack2(w1v, w1v), acc1);
        }
        float l0, h0, l1, h1;
        unpack2(acc0, l0, h0);
        unpack2(acc1, l1, h1);
        float sl = l0 + l1, sh = h0 + h1;
        float pl = __shfl_xor_sync(0xffffffffu, sl, 1);
        float ph = __shfl_xor_sync(0xffffffffu, sh, 1);
        if (half == 0) {
            int kg = c0 + k;
            float vA = sl + pl;
            float vB = sh + ph;
            __nv_bfloat16 hA = __float2bfloat16(vA);
            __nv_bfloat16 lA = __float2bfloat16(vA - __bfloat162float(hA));
            __nv_bfloat16 hB = __float2bfloat16(vB);
            __nv_bfloat16 lB = __float2bfloat16(vB - __bfloat162float(hB));
            u32 offA = w_off(256 + o, kg);
            u32 offB = w_off(288 + o, kg);
            *(__nv_bfloat16*)((char*)g_WH + offA) = hA;
            *(__nv_bfloat16*)((char*)g_WL + offA) = lA;
            *(__nv_bfloat16*)((char*)g_WH + offB) = hB;
            *(__nv_bfloat16*)((char*)g_WL + offB) = lB;
        }
    }

    if (b == 0) {
        int wid = tid >> 5, lane = tid & 31;
        if (wid < 8) {
            #pragma unroll
            for (int s = 0; s < 8; ++s) {
                int row = wid * 8 + s;
                int kind = row >> 5, o = row & 31;
                float p = 0.f;
                #pragma unroll
                for (int cc = 0; cc < 8; ++cc) {
                    int c = lane + 32 * cc;
                    p += w1_sm[o * 512 + 2 * c + kind] * b_sm[c];
                }
                #pragma unroll
                for (int off = 16; off > 0; off >>= 1)
                    p += __shfl_xor_sync(0xffffffffu, p, off);
                if (lane == 0) g_biasAll[256 + kind * 32 + o] = p;
            }
        }
        if (tid < 256) g_biasAll[tid] = b_sm[tid];
    }
}

// ---------------------------------------------------------------------------
// feat (bf16 3-pass, bulk-async staged): 320 CTAs.
// ---------------------------------------------------------------------------
__global__ __launch_bounds__(256) void feat_kernel() {
    extern __shared__ char fsm[];
    u32 sbase = smem_u32(fsm);
    int bx = blockIdx.x;
    int rg = bx >> 6, n = bx & 63;
    int tid = threadIdx.x, wid = tid >> 5, la = tid & 31;
    int wm = wid & 1, wn = wid >> 1;

    const char* wH = (const char*)g_WH + (size_t)rg * 65536;
    const char* wL = (const char*)g_WL + (size_t)rg * 65536;
    const char* xH = (const char*)g_xH + (size_t)n * 65536;
    const char* xL = (const char*)g_xL + (size_t)n * 65536;

    u32 mb0 = sbase + 65536, mb1 = sbase + 65544;
    if (tid == 0) {
        MBAR_INIT(mb0, 1u);
        MBAR_INIT(mb1, 1u);
    }
    __syncthreads();

    auto issue = [&](int kc, int buf) {
        u32 db = sbase + buf * 32768;
        u32 mb = buf ? mb1 : mb0;
        MBAR_EXPECT(mb, 32768u);
        BULK_G2S(db,         wH + (size_t)kc * 8192, 8192u, mb);
        BULK_G2S(db + 8192,  wL + (size_t)kc * 8192, 8192u, mb);
        BULK_G2S(db + 16384, xH + (size_t)kc * 8192, 8192u, mb);
        BULK_G2S(db + 24576, xL + (size_t)kc * 8192, 8192u, mb);
    };

    if (tid == 0) {
        issue(0, 0);
        issue(1, 1);
    }

    float acc[2][2][4];
    #pragma unroll
    for (int mt = 0; mt < 2; ++mt)
        #pragma unroll
        for (int nt = 0; nt < 2; ++nt)
            #pragma unroll
            for (int e = 0; e < 4; ++e) acc[mt][nt][e] = 0.f;

    int mrow_base = wm * 32 + (la & 7) + ((la >> 3) & 1) * 8;
    int a_kx = (la >> 4) * 16;
    int krow_loc = (la & 7) + ((la >> 3) & 1) * 8;
    int t_sw = (wn * 32 + ((la >> 4) & 1) * 16) ^ ((la & 7) << 4);

    int ph0 = 0, ph1 = 0;
    #pragma unroll 1
    for (int kc = 0; kc < 8; ++kc) {
        int buf = kc & 1;
        if (buf) { MBAR_WAIT(mb1, ph1); ph1 ^= 1; }
        else     { MBAR_WAIT(mb0, ph0); ph0 ^= 1; }
        u32 base = sbase + buf * 32768;
        u32 WHo = base, WLo = base + 8192, XHo = base + 16384, XLo = base + 24576;
        #pragma unroll
        for (int kk = 0; kk < 4; ++kk) {
            int kb = kk * 32;
            u32 offB = (u32)((kk * 16 + krow_loc) * 128) + (u32)t_sw;
            u32 bH[4], bL[4];
            LDSM4T(bH, XHo + offB);
            LDSM4T(bL, XLo + offB);
            #pragma unroll
            for (int mt = 0; mt < 2; ++mt) {
                int mr = mrow_base + mt * 16;
                u32 offA = (u32)mr * 128 + (((u32)(kb + a_kx)) ^ (((u32)mr & 7) << 4));
                u32 aH[4], aL[4];
                LDSM4(aH, WHo + offA);
                LDSM4(aL, WLo + offA);
                #pragma unroll
                for (int nt = 0; nt < 2; ++nt) {
                    int r0 = nt * 2;
                    MMA4(acc[mt][nt], aH, bH[r0], bH[r0 + 1]);
                    MMA4(acc[mt][nt], aH, bL[r0], bL[r0 + 1]);
                    MMA4(acc[mt][nt], aL, bH[r0], bH[r0 + 1]);
                }
            }
        }
        __syncthreads();
        if (kc + 2 < 8 && tid == 0) issue(kc + 2, buf);
    }

    char* feF = (char*)g_FeF + (size_t)n * 32768;
    char* gF  = (char*)g_GF + (size_t)n * 8192;
    int r0l = la >> 2, c0l = (la & 3) * 2;

    #pragma unroll
    for (int mt = 0; mt < 2; ++mt) {
        #pragma unroll
        for (int nt = 0; nt < 2; ++nt) {
            int t0 = wn * 16 + nt * 8 + c0l;
            #pragma unroll
            for (int hh = 0; hh < 2; ++hh) {
                int row = rg * 64 + wm * 32 + mt * 16 + r0l + hh * 8;
                float bias = g_biasAll[row];
                float v0 = acc[mt][nt][hh * 2 + 0] + bias;
                float v1 = acc[mt][nt][hh * 2 + 1] + bias;
                __half2 hv = __floats2half2_rn(v0, v1);
                u32 hbits = *(u32*)&hv;
                if (row < 256) {
                    int hw = row & 127;
                    int tp0 = (row < 128) ? t0 : (64 + t0);
                    u32 off = (u32)hw * 256 + (((u32)(tp0 * 2)) ^ (((u32)hw & 7) << 4));
                    *(u32*)(feF + off) = hbits;
                } else {
                    int o = (row < 288) ? (row - 256) : (row - 288);
                    int tp0 = (row < 288) ? t0 : (64 + t0);
                    u32 off = (u32)o * 256 + (((u32)(tp0 * 2)) ^ (((u32)o & 7) << 4));
                    *(u32*)(gF + off) = hbits;
                }
            }
        }
    }
}

// ---------------------------------------------------------------------------
// pair (fp16 single-pass): epilogue weights staged transposed in smem.
// ---------------------------------------------------------------------------
__global__ __launch_bounds__(512)
void pair_kernel(const float* __restrict__ b_c1,
                 const float* __restrict__ w_c2, const float* __restrict__ b_c2,
                 const float* __restrict__ w_fc1, const float* __restrict__ b_fc1,
                 const float* __restrict__ w_fc2, const float* __restrict__ b_fc2,
                 const float* __restrict__ w_fc3, const float* __restrict__ b_fc3,
                 const float* __restrict__ b_mlp,
                 float* __restrict__ out) {
    extern __shared__ char smem[];
    float* smf = (float*)smem;
    u32 sbase = smem_u32(smem);
    int tid = threadIdx.x;
    int wid = tid >> 5, la = tid & 31;
    int b = blockIdx.x;

    // epilogue tables (after mbar at byte 98304)
    float* wfc1T = smf + EPI_F;          // [64 m][32 o] : 2048
    float* wfc2T = wfc1T + 2048;         // [32 m][8 o]  : 256
    float* wc2s  = wfc2T + 256;          // [8 o2][32]   : 256
    float* bc1s  = wc2s + 256;           // 32
    float* bc2s  = bc1s + 32;            // 8
    float* bf1s  = bc2s + 8;             // 32
    float* bf2s  = bf1s + 32;            // 8
    float* bf3s  = bf2s + 8;             // 1

    int j = 1, bb = b;
    while (bb >= ((j + 7) >> 3)) { bb -= (j + 7) >> 3; ++j; }
    int i0 = bb * 8;

    u32 mb = sbase + 98304;
    if (tid == 0) MBAR_INIT(mb, 1u);
    __syncthreads();
    if (tid == 0) {
        MBAR_EXPECT(mb, 98304u);
        BULK_G2S(sbase, (const char*)g_FeF + (size_t)j * 32768, 32768u, mb);
        #pragma unroll
        for (int u = 0; u < 8; ++u) {
            int iu = i0 + u; if (iu >= j) iu = j - 1;
            BULK_G2S(sbase + 32768 + u * 8192, (const char*)g_GF + (size_t)iu * 8192, 8192u, mb);
        }
    }

    // stage epilogue tables (coalesced LDG, overlapped with bulk copies)
    #pragma unroll
    for (int k = 0; k < 4; ++k) {
        int idx = tid + k * 512;
        int o = idx >> 6, m = idx & 63;
        wfc1T[m * 32 + o] = w_fc1[idx];
    }
    if (tid < 256) {
        int o = tid >> 5, m = tid & 31;
        wfc2T[m * 8 + o] = w_fc2[tid];
        wc2s[tid] = w_c2[tid];
    } else if (tid < 288) {
        bc1s[tid - 256] = b_c1[tid - 256];
    } else if (tid < 320) {
        bf1s[tid - 288] = b_fc1[tid - 288];
    } else if (tid < 328) {
        bc2s[tid - 320] = b_c2[tid - 320];
    } else if (tid < 336) {
        bf2s[tid - 328] = b_fc2[tid - 328];
    } else if (tid == 336) {
        bf3s[0] = b_fc3[0];
    } else if (b < NSAMP && tid == 400) {
        float z = g_scorePart[2 * b] + g_scorePart[2 * b + 1] + b_mlp[0];
        out[b] = 1.f / (1.f + expf(-z));
    }
    __syncthreads();

    MBAR_WAIT(mb, 0u);

    int p = wid >> 1, half = wid & 1;
    u32 A_f = sbase;
    u32 B_f = sbase + 32768 + p * 8192;

    int mrow_base = half * 64 + (la & 7) + ((la >> 3) & 1) * 8;
    int a_kx = (la >> 4) * 16;
    int orow0 = ((la >> 4) & 1) * 8 + (la & 7);
    int b_kx = ((la >> 3) & 1) * 16;

    float acc[4][4][4];
    #pragma unroll
    for (int mt = 0; mt < 4; ++mt)
        #pragma unroll
        for (int nt = 0; nt < 4; ++nt)
            #pragma unroll
            for (int e = 0; e < 4; ++e) acc[mt][nt][e] = 0.f;

    #pragma unroll 2
    for (int ks = 0; ks < 8; ++ks) {
        int kb = ks * 32;
        u32 bF[2][4];
        #pragma unroll
        for (int q = 0; q < 2; ++q) {
            int orow = orow0 + q * 16;
            u32 off = (u32)orow * 256 + (((u32)(kb + b_kx)) ^ (((u32)orow & 7) << 4));
            LDSM4(bF[q], B_f + off);
        }
        #pragma unroll
        for (int mt = 0; mt < 4; ++mt) {
            int mr = mrow_base + mt * 16;
            u32 off = (u32)mr * 256 + (((u32)(kb + a_kx)) ^ (((u32)mr & 7) << 4));
            u32 aF[4];
            LDSM4(aF, A_f + off);
            #pragma unroll
            for (int nt = 0; nt < 4; ++nt) {
                int q = nt >> 1, r0 = (nt & 1) * 2;
                MMA4H(acc[mt][nt], aF, bF[q][r0], bF[q][r0 + 1]);
            }
        }
    }

    float bo[4][2];
    #pragma unroll
    for (int nt = 0; nt < 4; ++nt) {
        int o = nt * 8 + (la & 3) * 2;
        bo[nt][0] = bc1s[o];
        bo[nt][1] = bc1s[o + 1];
    }
    int r = la >> 2;
    bool writer = ((r & 5) == 0);
    int pw = (r >> 1) & 1;
    float* pool = smf + 8192 + p * 2048;

    asm volatile("bar.sync %0, 64;" :: "r"(1 + p));

    #pragma unroll
    for (int mt = 0; mt < 4; ++mt) {
        int ph0 = half * 8 + mt * 2;
        #pragma unroll
        for (int nt = 0; nt < 4; ++nt) {
            float v0 = acc[mt][nt][0], v1 = acc[mt][nt][1];
            float v2 = acc[mt][nt][2], v3 = acc[mt][nt][3];
            v0 = fmaxf(v0, __shfl_xor_sync(0xffffffffu, v0, 4));
            v0 = fmaxf(v0, __shfl_xor_sync(0xffffffffu, v0, 16));
            v1 = fmaxf(v1, __shfl_xor_sync(0xffffffffu, v1, 4));
            v1 = fmaxf(v1, __shfl_xor_sync(0xffffffffu, v1, 16));
            v2 = fmaxf(v2, __shfl_xor_sync(0xffffffffu, v2, 4));
            v2 = fmaxf(v2, __shfl_xor_sync(0xffffffffu, v2, 16));
            v3 = fmaxf(v3, __shfl_xor_sync(0xffffffffu, v3, 4));
            v3 = fmaxf(v3, __shfl_xor_sync(0xffffffffu, v3, 16));
            if (writer) {
                int o = nt * 8 + (la & 3) * 2;
                int s01 = ph0 * 2 + pw, s23 = (ph0 + 1) * 2 + pw;
                pool[s01 * 33 + o]     = v0 + bo[nt][0];
                pool[s01 * 33 + o + 1] = v1 + bo[nt][1];
                pool[s23 * 33 + o]     = v2 + bo[nt][0];
                pool[s23 * 33 + o + 1] = v3 + bo[nt][1];
            }
        }
    }

    int u = tid >> 6, t64 = tid & 63;
    bool valid = (i0 + u) < j;
    float* g2 = pool + 1056;
    float* vv = pool + 1312;
    float* v1s = pool + 1376;
    float* v2s = pool + 1408;
    int bar = 1 + u;

    asm volatile("bar.sync %0, 64;" :: "r"(bar));

    #pragma unroll
    for (int k = 0; k < 4; ++k) {
        int idx = t64 + k * 64;
        int o2 = idx >> 5, s2 = idx & 31;
        float sum = bc2s[o2];
        const float* wr = wc2s + o2 * 32;
        #pragma unroll
        for (int oo = 0; oo < 32; ++oo)
            sum += wr[oo] * pool[s2 * 33 + oo];
        g2[o2 * 32 + s2] = sum;
    }
    asm volatile("bar.sync %0, 64;" :: "r"(bar));

    {
        int o2 = t64 >> 3, q = t64 & 7;
        const float* gb = g2 + o2 * 32 + q * 4;
        vv[t64] = fmaxf(fmaxf(gb[0], gb[1]), fmaxf(gb[2], gb[3]));
    }
    asm volatile("bar.sync %0, 64;" :: "r"(bar));

    if (t64 < 32) {
        float z = bf1s[t64];
        #pragma unroll
        for (int m = 0; m < 64; ++m) z += wfc1T[m * 32 + t64] * vv[m];
        v1s[t64] = fmaxf(z, 0.f);
    }
    asm volatile("bar.sync %0, 64;" :: "r"(bar));
    if (t64 < 8) {
        float z = bf2s[t64];
        #pragma unroll
        for (int m = 0; m < 32; ++m) z += wfc2T[m * 8 + t64] * v1s[m];
        v2s[t64] = fmaxf(z, 0.f);
    }
    asm volatile("bar.sync %0, 64;" :: "r"(bar));
    if (t64 == 0 && valid) {
        float z = bf3s[0];
        #pragma unroll
        for (int m = 0; m < 8; ++m) z += w_fc3[m] * v2s[m];
        int i = i0 + u;
        int pidx = i * (2 * NSAMP - i - 1) / 2 + (j - i - 1);
        out[NSAMP + pidx] = 1.f / (1.f + expf(-z));
    }
}

extern "C" void kernel_launch(void* const* d_in, const int* in_sizes, int n_in,
                              void* d_out, int out_size) {
    const float* x        = (const float*)d_in[0];
    const float* w_conv1d = (const float*)d_in[1];
    const float* b_conv1d = (const float*)d_in[2];
    const float* w_c1     = (const float*)d_in[3];
    const float* b_c1     = (const float*)d_in[4];
    const float* w_c2     = (const float*)d_in[5];
    const float* b_c2     = (const float*)d_in[6];
    const float* w_fc1    = (const float*)d_in[7];
    const float* b_fc1    = (const float*)d_in[8];
    const float* w_fc2    = (const float*)d_in[9];
    const float* b_fc2    = (const float*)d_in[10];
    const float* w_fc3    = (const float*)d_in[11];
    const float* b_fc3    = (const float*)d_in[12];
    const float* w_mlp    = (const float*)d_in[13];
    const float* b_mlp    = (const float*)d_in[14];
    float* out = (float*)d_out;

    cudaFuncSetAttribute(prep_w_kernel, cudaFuncAttributeMaxDynamicSharedMemorySize, PREPW_SMEM_BYTES);
    cudaFuncSetAttribute(feat_kernel, cudaFuncAttributeMaxDynamicSharedMemorySize, FEAT_SMEM_BYTES);
    cudaFuncSetAttribute(pair_kernel, cudaFuncAttributeMaxDynamicSharedMemorySize, PAIR_SMEM_BYTES);

    prep_x_kernel<<<128, 512>>>(x, w_mlp);
    prep_w_kernel<<<64, 512, PREPW_SMEM_BYTES>>>(w_conv1d, b_conv1d, w_c1);
    feat_kernel<<<320, 256, FEAT_SMEM_BYTES>>>();
    pair_kernel<<<PAIR_BLOCKS, 512, PAIR_SMEM_BYTES>>>(b_c1, w_c2, b_c2, w_fc1, b_fc1,
                                                       w_fc2, b_fc2, w_fc3, b_fc3, b_mlp, out);
}